// round 16
// baseline (speedup 1.0000x reference)
#include <cuda_runtime.h>
#include <cuda_bf16.h>
#include <cstdint>

#define B_TOTAL  131072
#define DIM      1024
#define NH       21
#define THREADS  128
#define WROWS    16                  // rows per warp (1 m16 tile)
#define BROWS    64                  // rows per block (4 warps)
#define NTILES   (B_TOTAL / BROWS)   // 2048
#define NKS      (DIM / 16)          // 64 k16 steps
#define NT       3                   // n-tiles of 8 (21 -> 24)
#define NCTA     888                 // 148 SMs x 6 CTAs

// W fragments, k-permuted to match float4 lane loads.
// uint4 = {b0_hi, b1_hi, b0_lo, b1_lo}
__device__ uint4 g_wf[NKS][NT][32];
__device__ int   g_tile_ctr;

__global__ void prep_wfrag(const float* __restrict__ W)
{
    int idx = blockIdx.x * blockDim.x + threadIdx.x;
    if (idx == 0) g_tile_ctr = 0;
    if (idx >= NKS * NT * 32) return;
    int l  = idx & 31;
    int nt = (idx >> 5) % NT;
    int ks = idx / (NT * 32);
    int n  = nt * 8 + (l >> 2);
    int col = ks * 16 + 4 * (l & 3);
    float4 wv = make_float4(0.f, 0.f, 0.f, 0.f);
    if (n < NH) wv = *(const float4*)&W[(long long)n * DIM + col];
    uint32_t h0, h1, q0, q1;
    asm("cvt.rn.bf16x2.f32 %0, %1, %2;" : "=r"(h0) : "f"(wv.y), "f"(wv.x));
    asm("cvt.rn.bf16x2.f32 %0, %1, %2;" : "=r"(h1) : "f"(wv.w), "f"(wv.z));
    float rx = wv.x - __uint_as_float(h0 << 16);
    float ry = wv.y - __uint_as_float(h0 & 0xffff0000u);
    float rz = wv.z - __uint_as_float(h1 << 16);
    float rw = wv.w - __uint_as_float(h1 & 0xffff0000u);
    asm("cvt.rn.bf16x2.f32 %0, %1, %2;" : "=r"(q0) : "f"(ry), "f"(rx));
    asm("cvt.rn.bf16x2.f32 %0, %1, %2;" : "=r"(q1) : "f"(rw), "f"(rz));
    g_wf[ks][nt][l] = make_uint4(h0, h1, q0, q1);
}

#define MMA(c, a0, a1, a2, a3, b0, b1)                                          \
    asm("mma.sync.aligned.m16n8k16.row.col.f32.bf16.bf16.f32 "                  \
        "{%0,%1,%2,%3}, {%4,%5,%6,%7}, {%8,%9}, {%0,%1,%2,%3};"                 \
        : "+f"(c[0]), "+f"(c[1]), "+f"(c[2]), "+f"(c[3])                        \
        : "r"(a0), "r"(a1), "r"(a2), "r"(a3), "r"(b0), "r"(b1))

// float4 (4 consecutive k) -> two packed bf16x2 hi + two residual lo
__device__ __forceinline__ void cvt4(float4 v, uint32_t& h0, uint32_t& h1,
                                     uint32_t& q0, uint32_t& q1)
{
    asm("cvt.rn.bf16x2.f32 %0, %1, %2;" : "=r"(h0) : "f"(v.y), "f"(v.x));
    asm("cvt.rn.bf16x2.f32 %0, %1, %2;" : "=r"(h1) : "f"(v.w), "f"(v.z));
    float rx = v.x - __uint_as_float(h0 << 16);
    float ry = v.y - __uint_as_float(h0 & 0xffff0000u);
    float rz = v.z - __uint_as_float(h1 << 16);
    float rw = v.w - __uint_as_float(h1 & 0xffff0000u);
    asm("cvt.rn.bf16x2.f32 %0, %1, %2;" : "=r"(q0) : "f"(ry), "f"(rx));
    asm("cvt.rn.bf16x2.f32 %0, %1, %2;" : "=r"(q1) : "f"(rw), "f"(rz));
}

__global__ __launch_bounds__(THREADS, 6)
void linheads_mma_kernel(const float* __restrict__ x,
                         const float* __restrict__ v_conf,
                         const float* __restrict__ bias,
                         float* __restrict__ result,
                         float* __restrict__ out)
{
    __shared__ int s_tile;

    const int t   = threadIdx.x;
    const int wid = t >> 5;
    const int l   = t & 31;

    for (;;) {
        if (t == 0) s_tile = atomicAdd(&g_tile_ctr, 1);
        __syncthreads();
        const int tile = s_tile;
        __syncthreads();
        if (tile >= NTILES) break;

        const long long wb = (long long)tile * BROWS + wid * WROWS;
        // frag rows (r, r+8) <-> global rows (2r, 2r+1); lane quad-row r = l>>2
        const float* p00 = x + (wb + 2 * (l >> 2)) * DIM + 4 * (l & 3);

        float c[NT][4];
#pragma unroll
        for (int nt = 0; nt < NT; nt++)
#pragma unroll
            for (int i = 0; i < 4; i++) c[nt][i] = 0.f;

        // cur[rr]: float4 at (row wb + 2(l>>2) + rr, k 16ks + 4(l&3))
        float4 cur[2];
        cur[0] = __ldcs((const float4*)(p00));
        cur[1] = __ldcs((const float4*)(p00 + DIM));

#pragma unroll 4
        for (int ks = 0; ks < NKS; ks++) {
            float4 nxt[2];
            if (ks + 1 < NKS) {
                const int o = (ks + 1) * 16;
                nxt[0] = __ldcs((const float4*)(p00 + o));
                nxt[1] = __ldcs((const float4*)(p00 + DIM + o));
            }

            // a0 = hi(row rr0, k 4q..4q+1), a1 = row rr1, a2/a3 = k 4q+2..3
            uint32_t ah[4], al[4];
            cvt4(cur[0], ah[0], ah[2], al[0], al[2]);
            cvt4(cur[1], ah[1], ah[3], al[1], al[3]);

#pragma unroll
            for (int nt = 0; nt < NT; nt++) {
                uint4 wf = g_wf[ks][nt][l];
                MMA(c[nt], ah[0], ah[1], ah[2], ah[3], wf.x, wf.y);
                MMA(c[nt], ah[0], ah[1], ah[2], ah[3], wf.z, wf.w);
                MMA(c[nt], al[0], al[1], al[2], al[3], wf.x, wf.y);
            }

            cur[0] = nxt[0];
            cur[1] = nxt[1];
        }

        // ---- epilogue ----
        // c[nt][rr*2+e]: row = wb + 2(l>>2) + rr, col = nt*8 + 2(l&3) + e
#pragma unroll
        for (int rr = 0; rr < 2; rr++) {
            const long long row = wb + 2 * (l >> 2) + rr;
            float res = 0.f;
#pragma unroll
            for (int nt = 0; nt < NT; nt++) {
                int col0 = nt * 8 + 2 * (l & 3);
#pragma unroll
                for (int e = 0; e < 2; e++) {
                    int col = col0 + e;
                    if (col < NH) {
                        float o = c[nt][rr * 2 + e] + bias[col];
                        out[row * NH + col] = o;
                        res += o * v_conf[row * NH + col];
                    }
                }
            }
            res += __shfl_xor_sync(0xffffffffu, res, 1);
            res += __shfl_xor_sync(0xffffffffu, res, 2);
            if ((l & 3) == 0) result[row] = res;
        }
    }
}

extern "C" void kernel_launch(void* const* d_in, const int* in_sizes, int n_in,
                              void* d_out, int out_size)
{
    const float* x      = (const float*)d_in[0];   // [B, DIM]
    const float* v_conf = (const float*)d_in[1];   // [B, NH]
    const float* W      = (const float*)d_in[2];   // [NH, DIM]
    const float* bias   = (const float*)d_in[3];   // [NH]

    float* result = (float*)d_out;                 // [B]
    float* out    = (float*)d_out + B_TOTAL;       // [B, NH]

    prep_wfrag<<<(NKS * NT * 32 + 255) / 256, 256>>>(W);   // also resets tile counter

    linheads_mma_kernel<<<NCTA, THREADS>>>(x, v_conf, bias, result, out);
}

// round 17
// speedup vs baseline: 1.0365x; 1.0365x over previous
#include <cuda_runtime.h>
#include <cuda_bf16.h>
#include <cstdint>

#define B_TOTAL  131072
#define DIM      1024
#define NH       21
#define THREADS  128
#define WROWS    16                  // rows per warp (1 m16 tile)
#define BROWS    64                  // rows per block (4 warps)
#define NKS      (DIM / 16)          // 64 k16 steps
#define NT       3                   // n-tiles of 8 (21 -> 24)

// W fragments, k-permuted to match float4 lane loads.
// uint4 = {b0_hi, b1_hi, b0_lo, b1_lo}
__device__ uint4 g_wf[NKS][NT][32];

__global__ void prep_wfrag(const float* __restrict__ W)
{
    int idx = blockIdx.x * blockDim.x + threadIdx.x;
    if (idx >= NKS * NT * 32) return;
    int l  = idx & 31;
    int nt = (idx >> 5) % NT;
    int ks = idx / (NT * 32);
    int n  = nt * 8 + (l >> 2);
    int col = ks * 16 + 4 * (l & 3);
    float4 wv = make_float4(0.f, 0.f, 0.f, 0.f);
    if (n < NH) wv = *(const float4*)&W[(long long)n * DIM + col];
    uint32_t h0, h1, q0, q1;
    asm("cvt.rn.bf16x2.f32 %0, %1, %2;" : "=r"(h0) : "f"(wv.y), "f"(wv.x));
    asm("cvt.rn.bf16x2.f32 %0, %1, %2;" : "=r"(h1) : "f"(wv.w), "f"(wv.z));
    float rx = wv.x - __uint_as_float(h0 << 16);
    float ry = wv.y - __uint_as_float(h0 & 0xffff0000u);
    float rz = wv.z - __uint_as_float(h1 << 16);
    float rw = wv.w - __uint_as_float(h1 & 0xffff0000u);
    asm("cvt.rn.bf16x2.f32 %0, %1, %2;" : "=r"(q0) : "f"(ry), "f"(rx));
    asm("cvt.rn.bf16x2.f32 %0, %1, %2;" : "=r"(q1) : "f"(rw), "f"(rz));
    g_wf[ks][nt][l] = make_uint4(h0, h1, q0, q1);
}

#define MMA(c, a0, a1, a2, a3, b0, b1)                                          \
    asm("mma.sync.aligned.m16n8k16.row.col.f32.bf16.bf16.f32 "                  \
        "{%0,%1,%2,%3}, {%4,%5,%6,%7}, {%8,%9}, {%0,%1,%2,%3};"                 \
        : "+f"(c[0]), "+f"(c[1]), "+f"(c[2]), "+f"(c[3])                        \
        : "r"(a0), "r"(a1), "r"(a2), "r"(a3), "r"(b0), "r"(b1))

// float4 (4 consecutive k) -> two packed bf16x2 hi + two residual lo
__device__ __forceinline__ void cvt4(float4 v, uint32_t& h0, uint32_t& h1,
                                     uint32_t& q0, uint32_t& q1)
{
    asm("cvt.rn.bf16x2.f32 %0, %1, %2;" : "=r"(h0) : "f"(v.y), "f"(v.x));
    asm("cvt.rn.bf16x2.f32 %0, %1, %2;" : "=r"(h1) : "f"(v.w), "f"(v.z));
    float rx = v.x - __uint_as_float(h0 << 16);
    float ry = v.y - __uint_as_float(h0 & 0xffff0000u);
    float rz = v.z - __uint_as_float(h1 << 16);
    float rw = v.w - __uint_as_float(h1 & 0xffff0000u);
    asm("cvt.rn.bf16x2.f32 %0, %1, %2;" : "=r"(q0) : "f"(ry), "f"(rx));
    asm("cvt.rn.bf16x2.f32 %0, %1, %2;" : "=r"(q1) : "f"(rw), "f"(rz));
}

__device__ __forceinline__ float4 ldcs_off(const float* base, uint32_t byte_off)
{
    return __ldcs((const float4*)((const char*)base + byte_off));
}

__global__ __launch_bounds__(THREADS, 8)
void linheads_mma_kernel(const float* __restrict__ x,
                         const float* __restrict__ v_conf,
                         const float* __restrict__ bias,
                         float* __restrict__ result,
                         float* __restrict__ out)
{
    const int t   = threadIdx.x;
    const int wid = t >> 5;
    const int l   = t & 31;

    // 32-bit byte offsets: x spans 2^29 B, out 2^23.5 B -> all fit uint32
    const uint32_t wb = ((uint32_t)blockIdx.x * BROWS + (uint32_t)wid * WROWS);
    // frag rows (r, r+8) <-> global rows (2r, 2r+1); lane quad-row r = l>>2
    const uint32_t xoff0 = ((wb + 2u * (l >> 2)) * DIM + 4u * (l & 3)) * 4u;

    float c[NT][4];
#pragma unroll
    for (int nt = 0; nt < NT; nt++)
#pragma unroll
        for (int i = 0; i < 4; i++) c[nt][i] = 0.f;

    // cur[rr]: float4 at (row wb + 2(l>>2) + rr, k 16ks + 4(l&3))
    float4 cur[2];
    cur[0] = ldcs_off(x, xoff0);
    cur[1] = ldcs_off(x, xoff0 + DIM * 4u);

#pragma unroll 4
    for (int ks = 0; ks < NKS; ks++) {
        float4 nxt[2];
        if (ks + 1 < NKS) {
            const uint32_t o = xoff0 + (uint32_t)(ks + 1) * 64u;
            nxt[0] = ldcs_off(x, o);
            nxt[1] = ldcs_off(x, o + DIM * 4u);
        }

        // a0 = hi(row rr0, k 4q..4q+1), a1 = row rr1, a2/a3 = k 4q+2..3
        uint32_t ah[4], al[4];
        cvt4(cur[0], ah[0], ah[2], al[0], al[2]);
        cvt4(cur[1], ah[1], ah[3], al[1], al[3]);

#pragma unroll
        for (int nt = 0; nt < NT; nt++) {
            uint4 wf = g_wf[ks][nt][l];
            MMA(c[nt], ah[0], ah[1], ah[2], ah[3], wf.x, wf.y);
            MMA(c[nt], ah[0], ah[1], ah[2], ah[3], wf.z, wf.w);
            MMA(c[nt], al[0], al[1], al[2], al[3], wf.x, wf.y);
        }

        cur[0] = nxt[0];
        cur[1] = nxt[1];
    }

    // ---- epilogue ----
    // c[nt][rr*2+e]: row = wb + 2(l>>2) + rr, col = nt*8 + 2(l&3) + e
#pragma unroll
    for (int rr = 0; rr < 2; rr++) {
        const uint32_t row = wb + 2u * (l >> 2) + (uint32_t)rr;
        float res = 0.f;
#pragma unroll
        for (int nt = 0; nt < NT; nt++) {
            int col0 = nt * 8 + 2 * (l & 3);
#pragma unroll
            for (int e = 0; e < 2; e++) {
                int col = col0 + e;
                if (col < NH) {
                    float o = c[nt][rr * 2 + e] + bias[col];
                    out[row * NH + col] = o;
                    res += o * v_conf[row * NH + col];
                }
            }
        }
        res += __shfl_xor_sync(0xffffffffu, res, 1);
        res += __shfl_xor_sync(0xffffffffu, res, 2);
        if ((l & 3) == 0) result[row] = res;
    }
}

extern "C" void kernel_launch(void* const* d_in, const int* in_sizes, int n_in,
                              void* d_out, int out_size)
{
    const float* x      = (const float*)d_in[0];   // [B, DIM]
    const float* v_conf = (const float*)d_in[1];   // [B, NH]
    const float* W      = (const float*)d_in[2];   // [NH, DIM]
    const float* bias   = (const float*)d_in[3];   // [NH]

    float* result = (float*)d_out;                 // [B]
    float* out    = (float*)d_out + B_TOTAL;       // [B, NH]

    prep_wfrag<<<(NKS * NT * 32 + 255) / 256, 256>>>(W);

    dim3 grid(B_TOTAL / BROWS);                    // 2048
    linheads_mma_kernel<<<grid, THREADS>>>(x, v_conf, bias, result, out);
}